// round 1
// baseline (speedup 1.0000x reference)
#include <cuda_runtime.h>
#include <math.h>

#define NW 3
#define NH 16
#define DM 16
#define FF 64

// latent handoff between encoder and decoder kernels (no allocs allowed)
__device__ __align__(16) float g_latent[768];

__global__ __launch_bounds__(256) void enc_kernel(
    const float* __restrict__ t,
    const float* __restrict__ gat_W, const float* __restrict__ a_src, const float* __restrict__ a_dst,
    const float* __restrict__ te_W, const float* __restrict__ te_b, const float* __restrict__ pe,
    const float* __restrict__ qkv_W, const float* __restrict__ qkv_b,
    const float* __restrict__ out_W, const float* __restrict__ out_b,
    const float* __restrict__ ln1_g, const float* __restrict__ ln1_b,
    const float* __restrict__ ff1_W, const float* __restrict__ ff1_b,
    const float* __restrict__ ff2_W, const float* __restrict__ ff2_b,
    const float* __restrict__ ln2_g, const float* __restrict__ ln2_b)
{
    __shared__ float h_sh[NW][NH][DM];       // GAT features h; later reused as pre-LN tmp
    __shared__ float alpha_sh[NW][NH][NH];   // [w][dst][src]
    __shared__ float xe[NW][NH][DM];
    __shared__ float qkv_sh[NW][NH][48];
    __shared__ float ctx_sh[NW][NH][DM];     // gat_out temp, then attention context
    __shared__ float hid_sh[NW][NH][FF];
    __shared__ float esrc[48], edst[48];

    const int tid = threadIdx.x;

    // ---- 1. h = x @ gat_W  (x: (w,n,3), gat_W: (3,16)) ----
    for (int idx = tid; idx < NW*NH*DM; idx += 256) {
        int w = idx / (NH*DM), n = (idx / DM) % NH, f = idx % DM;
        const float* xr = t + (w*NH + n)*3;
        h_sh[w][n][f] = xr[0]*gat_W[0*DM+f] + xr[1]*gat_W[1*DM+f] + xr[2]*gat_W[2*DM+f];
    }
    __syncthreads();

    // ---- 2. e_src / e_dst = h @ a ----
    if (tid < 96) {
        int which = tid / 48, idx = tid % 48;
        int w = idx / NH, n = idx % NH;
        const float* a = which ? a_dst : a_src;
        float s = 0.f;
        #pragma unroll
        for (int f = 0; f < DM; f++) s += h_sh[w][n][f]*a[f];
        if (which) edst[idx] = s; else esrc[idx] = s;
    }
    __syncthreads();

    // ---- 3. alpha = softmax over sources, per (w,dst) ----
    if (tid < 48) {
        int w = tid / NH, d = tid % NH;
        float ed = edst[w*NH+d];
        float vals[NH], mx = -1e30f;
        #pragma unroll
        for (int s = 0; s < NH; s++) {
            float e = esrc[w*NH+s] + ed;
            e = (e > 0.f) ? e : 0.2f*e;   // leaky_relu(0.2)
            vals[s] = e; mx = fmaxf(mx, e);
        }
        float sum = 0.f;
        #pragma unroll
        for (int s = 0; s < NH; s++) { vals[s] = __expf(vals[s]-mx); sum += vals[s]; }
        float inv = 1.f/sum;
        #pragma unroll
        for (int s = 0; s < NH; s++) alpha_sh[w][d][s] = vals[s]*inv;
    }
    __syncthreads();

    // ---- 4. gat_out[w,d,f] = elu( sum_s alpha[w,d,s]*h[w,s,f] ) -> ctx_sh temp ----
    for (int idx = tid; idx < NW*NH*DM; idx += 256) {
        int w = idx/(NH*DM), d2 = (idx/DM)%NH, f = idx%DM;
        float s = 0.f;
        #pragma unroll
        for (int s_ = 0; s_ < NH; s_++) s += alpha_sh[w][d2][s_]*h_sh[w][s_][f];
        ctx_sh[w][d2][f] = (s > 0.f) ? s : (__expf(s) - 1.f);   // elu
    }
    __syncthreads();

    // ---- 5. xe = gat_out @ te_W^T + te_b + pe ----
    for (int idx = tid; idx < NW*NH*DM; idx += 256) {
        int w = idx/(NH*DM), n = (idx/DM)%NH, d = idx%DM;
        float s = te_b[d] + pe[w*DM+d];
        #pragma unroll
        for (int f = 0; f < DM; f++) s += ctx_sh[w][n][f]*te_W[d*DM+f];
        xe[w][n][d] = s;
    }
    __syncthreads();

    const float inv_sqrt_hd = 0.35355339059327373f; // 1/sqrt(8)

    for (int l = 0; l < 2; l++) {
        const float* qW = qkv_W + l*48*DM;
        const float* qb = qkv_b + l*48;
        // ---- qkv ----
        for (int idx = tid; idx < NW*NH*48; idx += 256) {
            int w = idx/(NH*48), n = (idx/48)%NH, j = idx%48;
            float s = qb[j];
            #pragma unroll
            for (int i = 0; i < DM; i++) s += xe[w][n][i]*qW[j*DM+i];
            qkv_sh[w][n][j] = s;
        }
        __syncthreads();
        // ---- attention: one thread per (b, head, query-pos) = 96 units ----
        if (tid < 96) {
            int b = tid/6, h = (tid%6)/3, qs = tid%3;
            const float* q = &qkv_sh[qs][b][h*8];
            float sc[3], mx = -1e30f;
            #pragma unroll
            for (int ks = 0; ks < 3; ks++) {
                const float* k = &qkv_sh[ks][b][16 + h*8];
                float s = 0.f;
                #pragma unroll
                for (int e = 0; e < 8; e++) s += q[e]*k[e];
                s *= inv_sqrt_hd;
                sc[ks] = s; mx = fmaxf(mx, s);
            }
            float sum = 0.f;
            #pragma unroll
            for (int ks = 0; ks < 3; ks++) { sc[ks] = __expf(sc[ks]-mx); sum += sc[ks]; }
            float inv = 1.f/sum;
            #pragma unroll
            for (int e = 0; e < 8; e++) {
                float c = 0.f;
                #pragma unroll
                for (int ks = 0; ks < 3; ks++) c += sc[ks]*qkv_sh[ks][b][32 + h*8 + e];
                ctx_sh[qs][b][h*8+e] = c*inv;
            }
        }
        __syncthreads();
        // ---- residual + out-proj -> h_sh tmp ----
        const float* oW = out_W + l*DM*DM;
        const float* ob = out_b + l*DM;
        for (int idx = tid; idx < NW*NH*DM; idx += 256) {
            int w = idx/(NH*DM), n = (idx/DM)%NH, d = idx%DM;
            float s = ob[d] + xe[w][n][d];
            #pragma unroll
            for (int i = 0; i < DM; i++) s += ctx_sh[w][n][i]*oW[d*DM+i];
            h_sh[w][n][d] = s;
        }
        __syncthreads();
        // ---- LN1 -> xe ----
        if (tid < 48) {
            int w = tid/NH, n = tid%NH;
            float m = 0.f;
            #pragma unroll
            for (int d = 0; d < DM; d++) m += h_sh[w][n][d];
            m *= (1.f/DM);
            float v = 0.f;
            #pragma unroll
            for (int d = 0; d < DM; d++) { float df = h_sh[w][n][d]-m; v += df*df; }
            v *= (1.f/DM);
            float r = rsqrtf(v + 1e-5f);
            #pragma unroll
            for (int d = 0; d < DM; d++)
                xe[w][n][d] = (h_sh[w][n][d]-m)*r*ln1_g[l*DM+d] + ln1_b[l*DM+d];
        }
        __syncthreads();
        // ---- ff1 (relu) ----
        const float* f1W = ff1_W + l*FF*DM;
        const float* f1b = ff1_b + l*FF;
        for (int idx = tid; idx < NW*NH*FF; idx += 256) {
            int w = idx/(NH*FF), n = (idx/FF)%NH, f = idx%FF;
            float s = f1b[f];
            #pragma unroll
            for (int d = 0; d < DM; d++) s += xe[w][n][d]*f1W[f*DM+d];
            hid_sh[w][n][f] = fmaxf(s, 0.f);
        }
        __syncthreads();
        // ---- ff2 + residual -> h_sh ----
        const float* f2W = ff2_W + l*DM*FF;
        const float* f2b = ff2_b + l*DM;
        for (int idx = tid; idx < NW*NH*DM; idx += 256) {
            int w = idx/(NH*DM), n = (idx/DM)%NH, d = idx%DM;
            float s = f2b[d] + xe[w][n][d];
            #pragma unroll
            for (int f = 0; f < FF; f++) s += hid_sh[w][n][f]*f2W[d*FF+f];
            h_sh[w][n][d] = s;
        }
        __syncthreads();
        // ---- LN2 -> xe ----
        if (tid < 48) {
            int w = tid/NH, n = tid%NH;
            float m = 0.f;
            #pragma unroll
            for (int d = 0; d < DM; d++) m += h_sh[w][n][d];
            m *= (1.f/DM);
            float v = 0.f;
            #pragma unroll
            for (int d = 0; d < DM; d++) { float df = h_sh[w][n][d]-m; v += df*df; }
            v *= (1.f/DM);
            float r = rsqrtf(v + 1e-5f);
            #pragma unroll
            for (int d = 0; d < DM; d++)
                xe[w][n][d] = (h_sh[w][n][d]-m)*r*ln2_g[l*DM+d] + ln2_b[l*DM+d];
        }
        __syncthreads();
    }

    // ---- latent: batch(host)-major  latent[b*48 + s*16 + d] = xe[s][b][d] ----
    for (int idx = tid; idx < 768; idx += 256) {
        int w = idx/(NH*DM), n = (idx/DM)%NH, d = idx%DM;
        g_latent[n*48 + w*16 + d] = xe[w][n][d];
    }
}

// Decoder: 160 output rows, one warp per row, K-split across lanes (float4).
__global__ __launch_bounds__(256) void dec_kernel(
    const float* __restrict__ an_W, const float* __restrict__ an_b,
    const float* __restrict__ pr_W, const float* __restrict__ pr_b,
    float* __restrict__ out)
{
    int warp = blockIdx.x * 8 + (threadIdx.x >> 5);
    int lane = threadIdx.x & 31;
    const float4* lat4 = (const float4*)g_latent;

    const float4* wrow;
    float bias;
    bool sig;
    if (warp < 32) { wrow = (const float4*)(an_W + warp*768); bias = an_b[warp]; sig = false; }
    else           { int o = warp - 32;
                     wrow = (const float4*)(pr_W + o*768);    bias = pr_b[o];    sig = true; }

    float s = 0.f;
    #pragma unroll
    for (int i = 0; i < 6; i++) {
        int j = i*32 + lane;               // lanes contiguous -> coalesced 128B/line
        float4 w4 = wrow[j];
        float4 x4 = lat4[j];
        s += w4.x*x4.x + w4.y*x4.y + w4.z*x4.z + w4.w*x4.w;
    }
    #pragma unroll
    for (int off = 16; off; off >>= 1) s += __shfl_down_sync(0xffffffffu, s, off);

    if (lane == 0) {
        s += bias;
        if (sig) s = 1.f / (1.f + __expf(-s));
        out[warp] = s;                     // [0,32): anomaly, [32,160): proto
    }
}

extern "C" void kernel_launch(void* const* d_in, const int* in_sizes, int n_in,
                              void* d_out, int out_size) {
    // input order: t, s(unused), gat_W, gat_a_src, gat_a_dst, te_W, te_b, pe,
    // qkv_W, qkv_b, out_W, out_b, ln1_g, ln1_b, ff1_W, ff1_b, ff2_W, ff2_b,
    // ln2_g, ln2_b, an_W, an_b, pr_W, pr_b
    enc_kernel<<<1, 256>>>(
        (const float*)d_in[0],
        (const float*)d_in[2], (const float*)d_in[3], (const float*)d_in[4],
        (const float*)d_in[5], (const float*)d_in[6], (const float*)d_in[7],
        (const float*)d_in[8], (const float*)d_in[9],
        (const float*)d_in[10], (const float*)d_in[11],
        (const float*)d_in[12], (const float*)d_in[13],
        (const float*)d_in[14], (const float*)d_in[15],
        (const float*)d_in[16], (const float*)d_in[17],
        (const float*)d_in[18], (const float*)d_in[19]);

    dec_kernel<<<20, 256>>>(
        (const float*)d_in[20], (const float*)d_in[21],
        (const float*)d_in[22], (const float*)d_in[23],
        (float*)d_out);
}

// round 2
// speedup vs baseline: 2.1478x; 2.1478x over previous
#include <cuda_runtime.h>
#include <math.h>

#define NW 3
#define NH 16
#define DM 16
#define FFD 64
#define NT 512
#define DEC_BLOCKS 10

// handoff state (device globals: allocation-free, zero-initialized at load)
__device__ __align__(16) float g_latent[768];
__device__ int g_flag;
__device__ int g_done;

__device__ __forceinline__ float dot16(const float* __restrict__ a, const float* __restrict__ b) {
    const float4* a4 = (const float4*)a;
    const float4* b4 = (const float4*)b;
    float s = 0.f;
#pragma unroll
    for (int i = 0; i < 4; i++) {
        float4 x = a4[i], y = b4[i];
        s += x.x*y.x + x.y*y.y + x.z*y.z + x.w*y.w;
    }
    return s;
}

__global__ __launch_bounds__(NT, 1) void fused_kernel(
    const float* __restrict__ t,
    const float* __restrict__ gat_W, const float* __restrict__ a_src, const float* __restrict__ a_dst,
    const float* __restrict__ te_W, const float* __restrict__ te_b, const float* __restrict__ pe,
    const float* __restrict__ qkv_W, const float* __restrict__ qkv_b,
    const float* __restrict__ out_W, const float* __restrict__ out_b,
    const float* __restrict__ ln1_g, const float* __restrict__ ln1_b,
    const float* __restrict__ ff1_W, const float* __restrict__ ff1_b,
    const float* __restrict__ ff2_W, const float* __restrict__ ff2_b,
    const float* __restrict__ ln2_g, const float* __restrict__ ln2_b,
    const float* __restrict__ an_W, const float* __restrict__ an_b,
    const float* __restrict__ pr_W, const float* __restrict__ pr_b,
    float* __restrict__ out)
{
    // ================= DECODER BLOCKS (0..9) =================
    if (blockIdx.x < DEC_BLOCKS) {
        int warp = blockIdx.x * 16 + (threadIdx.x >> 5);   // 0..159
        int lane = threadIdx.x & 31;

        const float* wr;
        float bias;
        bool sig;
        if (warp < 32) { wr = an_W + warp * 768;        bias = an_b[warp];      sig = false; }
        else           { wr = pr_W + (warp - 32) * 768; bias = pr_b[warp - 32]; sig = true;  }

        // prefetch weights into registers while encoder runs
        const float4* w4p = (const float4*)wr;
        float4 w[6];
#pragma unroll
        for (int i = 0; i < 6; i++) w[i] = w4p[i * 32 + lane];

        // spin (lane 0 only), then acquire
        if (lane == 0) {
            volatile int* fl = &g_flag;
            while (*fl == 0) { __nanosleep(64); }
        }
        __syncwarp();
        __threadfence();

        const float4* lat4 = (const float4*)g_latent;
        float s = 0.f;
#pragma unroll
        for (int i = 0; i < 6; i++) {
            float4 x = __ldcg(&lat4[i * 32 + lane]);
            s += w[i].x*x.x + w[i].y*x.y + w[i].z*x.z + w[i].w*x.w;
        }
#pragma unroll
        for (int o = 16; o; o >>= 1) s += __shfl_down_sync(0xffffffffu, s, o);

        if (lane == 0) {
            s += bias;
            if (sig) s = 1.f / (1.f + __expf(-s));
            out[warp] = s;
        }

        // reset protocol: last finished dec block restores initial state
        __syncthreads();
        if (threadIdx.x == 0) {
            int d = atomicAdd(&g_done, 1);
            if (d == DEC_BLOCKS - 1) {
                g_done = 0;
                __threadfence();
                *(volatile int*)&g_flag = 0;
            }
        }
        return;
    }

    // ================= ENCODER BLOCK (10) =================
    extern __shared__ float sm[];
    // weights (padded rows: stride 20 for 16-wide rows, 68 for 64-wide rows)
    float* s_t    = sm;            // 144
    float* s_gatW = sm + 144;      // 48
    float* s_as   = sm + 192;      // 16
    float* s_ad   = sm + 208;      // 16
    float* s_teW  = sm + 224;      // 320  (16 rows * 20)
    float* s_teb  = sm + 544;      // 16
    float* s_pe   = sm + 560;      // 48
    float* s_qkvW = sm + 608;      // 1920 (2*48 rows * 20)
    float* s_qkvb = sm + 2528;     // 96
    float* s_outW = sm + 2624;     // 640  (2*16 rows * 20)
    float* s_outb = sm + 3264;     // 32
    float* s_ln1g = sm + 3296;     // 32
    float* s_ln1b = sm + 3328;     // 32
    float* s_ff1W = sm + 3360;     // 2560 (2*64 rows * 20)
    float* s_ff1b = sm + 5920;     // 128
    float* s_ff2W = sm + 6048;     // 2176 (2*16 rows * 68)
    float* s_ff2b = sm + 8224;     // 32
    float* s_ln2g = sm + 8256;     // 32
    float* s_ln2b = sm + 8288;     // 32
    // activations
    float* A_h    = sm + 8320;     // 768  [w][n][16]
    float* A_al   = sm + 9088;     // 768  [w][dst][src]
    float* A_xe   = sm + 9856;     // 768  [w][n][16]
    float* A_qkv  = sm + 10624;    // 2304 [w][n][48]
    float* A_ctx  = sm + 12928;    // 768  [w][n][16]
    float* A_hid  = sm + 13696;    // 3072 [w][n][64]
    float* A_e    = sm + 16768;    // 96  (esrc 0..47, edst 48..95)

    const int tid = threadIdx.x;

    // ---- preload everything (coalesced, high MLP, one time) ----
    for (int i = tid; i < 144; i += NT) s_t[i] = t[i];
    for (int i = tid; i < 48; i += NT)  s_gatW[i] = gat_W[i];
    if (tid < 16) { s_as[tid] = a_src[tid]; s_ad[tid] = a_dst[tid]; s_teb[tid] = te_b[tid]; }
    for (int i = tid; i < 256; i += NT)  s_teW[(i >> 4) * 20 + (i & 15)] = te_W[i];
    for (int i = tid; i < 48; i += NT)   s_pe[i] = pe[i];
    for (int i = tid; i < 1536; i += NT) s_qkvW[(i >> 4) * 20 + (i & 15)] = qkv_W[i];
    for (int i = tid; i < 96; i += NT)   s_qkvb[i] = qkv_b[i];
    for (int i = tid; i < 512; i += NT)  s_outW[(i >> 4) * 20 + (i & 15)] = out_W[i];
    if (tid < 32) {
        s_outb[tid] = out_b[tid];
        s_ln1g[tid] = ln1_g[tid]; s_ln1b[tid] = ln1_b[tid];
        s_ln2g[tid] = ln2_g[tid]; s_ln2b[tid] = ln2_b[tid];
        s_ff2b[tid] = ff2_b[tid];
    }
    for (int i = tid; i < 2048; i += NT) s_ff1W[(i >> 4) * 20 + (i & 15)] = ff1_W[i];
    for (int i = tid; i < 128; i += NT)  s_ff1b[i] = ff1_b[i];
    for (int i = tid; i < 2048; i += NT) s_ff2W[(i >> 6) * 68 + (i & 63)] = ff2_W[i];
    __syncthreads();

    // ---- GAT: h = x @ gat_W ----
    for (int idx = tid; idx < 768; idx += NT) {
        int w = idx >> 8, rem = idx & 255, n = rem >> 4, f = rem & 15;
        const float* xr = s_t + (w * 16 + n) * 3;
        A_h[idx] = xr[0] * s_gatW[f] + xr[1] * s_gatW[16 + f] + xr[2] * s_gatW[32 + f];
    }
    __syncthreads();

    // ---- e_src / e_dst ----
    if (tid < 96) {
        int which = tid >= 48, idx = tid - which * 48;
        A_e[tid] = dot16(A_h + idx * 16, which ? s_ad : s_as);
    }
    __syncthreads();

    // ---- alpha = softmax over sources per (w,dst) ----
    if (tid < 48) {
        int w = tid >> 4, d = tid & 15;
        float ed = A_e[48 + tid];
        float vals[16], mx = -1e30f;
#pragma unroll
        for (int s = 0; s < 16; s++) {
            float e = A_e[w * 16 + s] + ed;
            e = (e > 0.f) ? e : 0.2f * e;
            vals[s] = e; mx = fmaxf(mx, e);
        }
        float sum = 0.f;
#pragma unroll
        for (int s = 0; s < 16; s++) { vals[s] = __expf(vals[s] - mx); sum += vals[s]; }
        float inv = 1.f / sum;
#pragma unroll
        for (int s = 0; s < 16; s++) A_al[w * 256 + d * 16 + s] = vals[s] * inv;
    }
    __syncthreads();

    // ---- gat_out = elu(alpha^T agg) -> A_ctx ----
    for (int idx = tid; idx < 768; idx += NT) {
        int w = idx >> 8, rem = idx & 255, d = rem >> 4, f = rem & 15;
        float s = 0.f;
        const float* al = A_al + w * 256 + d * 16;
        const float* hh = A_h + w * 256 + f;
#pragma unroll
        for (int ss = 0; ss < 16; ss++) s += al[ss] * hh[ss * 16];
        A_ctx[idx] = (s > 0.f) ? s : (__expf(s) - 1.f);
    }
    __syncthreads();

    // ---- xe = gat_out @ te_W^T + te_b + pe ----
    for (int idx = tid; idx < 768; idx += NT) {
        int w = idx >> 8, rem = idx & 255, n = rem >> 4, d = rem & 15;
        A_xe[idx] = s_teb[d] + s_pe[w * 16 + d] + dot16(A_ctx + w * 256 + n * 16, s_teW + d * 20);
    }
    __syncthreads();

    const float inv_sqrt_hd = 0.35355339059327373f;

    for (int l = 0; l < 2; l++) {
        // ---- qkv ----
        for (int idx = tid; idx < 2304; idx += NT) {
            int w = idx / 768, rem = idx - w * 768, n = rem / 48, j = rem - n * 48;
            A_qkv[idx] = s_qkvb[l * 48 + j] + dot16(A_xe + w * 256 + n * 16, s_qkvW + l * 960 + j * 20);
        }
        __syncthreads();
        // ---- attention (96 units: b x head x query) ----
        if (tid < 96) {
            int b = tid / 6, r = tid - b * 6, h = r >> 1 ? 0 : 0, dummy = 0;
            (void)h; (void)dummy;
            int hh = r / 3, qs = r - hh * 3;
            const float* q = A_qkv + qs * 768 + b * 48 + hh * 8;
            float sc[3], mx = -1e30f;
#pragma unroll
            for (int ks = 0; ks < 3; ks++) {
                const float* k = A_qkv + ks * 768 + b * 48 + 16 + hh * 8;
                float s = 0.f;
#pragma unroll
                for (int e = 0; e < 8; e++) s += q[e] * k[e];
                s *= inv_sqrt_hd;
                sc[ks] = s; mx = fmaxf(mx, s);
            }
            float sum = 0.f;
#pragma unroll
            for (int ks = 0; ks < 3; ks++) { sc[ks] = __expf(sc[ks] - mx); sum += sc[ks]; }
            float inv = 1.f / sum;
#pragma unroll
            for (int e = 0; e < 8; e++) {
                float c = 0.f;
#pragma unroll
                for (int ks = 0; ks < 3; ks++) c += sc[ks] * A_qkv[ks * 768 + b * 48 + 32 + hh * 8 + e];
                A_ctx[qs * 256 + b * 16 + hh * 8 + e] = c * inv;
            }
        }
        __syncthreads();
        // ---- out-proj + residual -> A_h ----
        for (int idx = tid; idx < 768; idx += NT) {
            int w = idx >> 8, rem = idx & 255, n = rem >> 4, d = rem & 15;
            A_h[idx] = s_outb[l * 16 + d] + A_xe[idx] +
                       dot16(A_ctx + w * 256 + n * 16, s_outW + l * 320 + d * 20);
        }
        __syncthreads();
        // ---- LN1 -> A_xe ----
        if (tid < 48) {
            int base = tid * 16;
            float x[16];
#pragma unroll
            for (int i = 0; i < 4; i++) {
                float4 v = ((const float4*)(A_h + base))[i];
                x[4*i] = v.x; x[4*i+1] = v.y; x[4*i+2] = v.z; x[4*i+3] = v.w;
            }
            float m = 0.f;
#pragma unroll
            for (int e = 0; e < 16; e++) m += x[e];
            m *= 0.0625f;
            float v = 0.f;
#pragma unroll
            for (int e = 0; e < 16; e++) { float d = x[e] - m; v += d * d; }
            float rin = rsqrtf(v * 0.0625f + 1e-5f);
            const float* g = s_ln1g + l * 16;
            const float* bb = s_ln1b + l * 16;
#pragma unroll
            for (int e = 0; e < 16; e++) A_xe[base + e] = (x[e] - m) * rin * g[e] + bb[e];
        }
        __syncthreads();
        // ---- ff1 (relu) ----
        for (int idx = tid; idx < 3072; idx += NT) {
            int w = idx >> 10, rem = idx & 1023, n = rem >> 6, f = rem & 63;
            float s = s_ff1b[l * 64 + f] + dot16(A_xe + w * 256 + n * 16, s_ff1W + l * 1280 + f * 20);
            A_hid[idx] = fmaxf(s, 0.f);
        }
        __syncthreads();
        // ---- ff2 + residual -> A_h ----
        for (int idx = tid; idx < 768; idx += NT) {
            int w = idx >> 8, rem = idx & 255, n = rem >> 4, d = rem & 15;
            const float4* hr = (const float4*)(A_hid + w * 1024 + n * 64);
            const float4* wr = (const float4*)(s_ff2W + l * 1088 + d * 68);
            float s = s_ff2b[l * 16 + d] + A_xe[idx];
#pragma unroll
            for (int i = 0; i < 16; i++) {
                float4 a = hr[i], b = wr[i];
                s += a.x*b.x + a.y*b.y + a.z*b.z + a.w*b.w;
            }
            A_h[idx] = s;
        }
        __syncthreads();
        // ---- LN2 -> A_xe ----
        if (tid < 48) {
            int base = tid * 16;
            float x[16];
#pragma unroll
            for (int i = 0; i < 4; i++) {
                float4 v = ((const float4*)(A_h + base))[i];
                x[4*i] = v.x; x[4*i+1] = v.y; x[4*i+2] = v.z; x[4*i+3] = v.w;
            }
            float m = 0.f;
#pragma unroll
            for (int e = 0; e < 16; e++) m += x[e];
            m *= 0.0625f;
            float v = 0.f;
#pragma unroll
            for (int e = 0; e < 16; e++) { float d = x[e] - m; v += d * d; }
            float rin = rsqrtf(v * 0.0625f + 1e-5f);
            const float* g = s_ln2g + l * 16;
            const float* bb = s_ln2b + l * 16;
#pragma unroll
            for (int e = 0; e < 16; e++) A_xe[base + e] = (x[e] - m) * rin * g[e] + bb[e];
        }
        __syncthreads();
    }

    // ---- latent (host-major) to global, then release flag ----
    for (int idx = tid; idx < 768; idx += NT) {
        int w = idx >> 8, rem = idx & 255, n = rem >> 4, d = rem & 15;
        g_latent[n * 48 + w * 16 + d] = A_xe[idx];
    }
    __threadfence();
    __syncthreads();
    if (tid == 0) *(volatile int*)&g_flag = 1;
}

extern "C" void kernel_launch(void* const* d_in, const int* in_sizes, int n_in,
                              void* d_out, int out_size) {
    // inputs: t, s(unused), gat_W, gat_a_src, gat_a_dst, te_W, te_b, pe,
    // qkv_W, qkv_b, out_W, out_b, ln1_g, ln1_b, ff1_W, ff1_b, ff2_W, ff2_b,
    // ln2_g, ln2_b, an_W, an_b, pr_W, pr_b
    const int smem_bytes = 16864 * 4;
    cudaFuncSetAttribute(fused_kernel, cudaFuncAttributeMaxDynamicSharedMemorySize, smem_bytes);
    fused_kernel<<<DEC_BLOCKS + 1, NT, smem_bytes>>>(
        (const float*)d_in[0],
        (const float*)d_in[2], (const float*)d_in[3], (const float*)d_in[4],
        (const float*)d_in[5], (const float*)d_in[6], (const float*)d_in[7],
        (const float*)d_in[8], (const float*)d_in[9],
        (const float*)d_in[10], (const float*)d_in[11],
        (const float*)d_in[12], (const float*)d_in[13],
        (const float*)d_in[14], (const float*)d_in[15],
        (const float*)d_in[16], (const float*)d_in[17],
        (const float*)d_in[18], (const float*)d_in[19],
        (const float*)d_in[20], (const float*)d_in[21],
        (const float*)d_in[22], (const float*)d_in[23],
        (float*)d_out);
}

// round 3
// speedup vs baseline: 2.4054x; 1.1199x over previous
#include <cuda_runtime.h>
#include <math.h>

#define NT 512
#define DEC_BLOCKS 10

// handoff state (device globals: allocation-free)
__device__ __align__(16) float g_latent[768];
__device__ int g_flag;
__device__ int g_done;

__global__ __launch_bounds__(NT, 1) void fused_kernel(
    const float* __restrict__ t,
    const float* __restrict__ gat_W, const float* __restrict__ a_src, const float* __restrict__ a_dst,
    const float* __restrict__ te_W, const float* __restrict__ te_b, const float* __restrict__ pe,
    const float* __restrict__ qkv_W, const float* __restrict__ qkv_b,
    const float* __restrict__ out_W, const float* __restrict__ out_b,
    const float* __restrict__ ln1_g, const float* __restrict__ ln1_b,
    const float* __restrict__ ff1_W, const float* __restrict__ ff1_b,
    const float* __restrict__ ff2_W, const float* __restrict__ ff2_b,
    const float* __restrict__ ln2_g, const float* __restrict__ ln2_b,
    const float* __restrict__ an_W, const float* __restrict__ an_b,
    const float* __restrict__ pr_W, const float* __restrict__ pr_b,
    float* __restrict__ out)
{
    // ================= DECODER BLOCKS (0..9) =================
    if (blockIdx.x < DEC_BLOCKS) {
        int warp = blockIdx.x * 16 + (threadIdx.x >> 5);   // 0..159
        int lane = threadIdx.x & 31;

        const float* wr;
        float bias;
        bool sig;
        if (warp < 32) { wr = an_W + warp * 768;        bias = an_b[warp];      sig = false; }
        else           { wr = pr_W + (warp - 32) * 768; bias = pr_b[warp - 32]; sig = true;  }

        const float4* w4p = (const float4*)wr;
        float4 w[6];
#pragma unroll
        for (int i = 0; i < 6; i++) w[i] = w4p[i * 32 + lane];

        if (lane == 0) {
            volatile int* fl = &g_flag;
            while (*fl == 0) { __nanosleep(32); }
        }
        __syncwarp();
        __threadfence();

        const float4* lat4 = (const float4*)g_latent;
        float s = 0.f;
#pragma unroll
        for (int i = 0; i < 6; i++) {
            float4 x = __ldcg(&lat4[i * 32 + lane]);
            s += w[i].x*x.x + w[i].y*x.y + w[i].z*x.z + w[i].w*x.w;
        }
#pragma unroll
        for (int o = 16; o; o >>= 1) s += __shfl_down_sync(0xffffffffu, s, o);

        if (lane == 0) {
            s += bias;
            if (sig) s = 1.f / (1.f + __expf(-s));
            out[warp] = s;
        }

        __syncthreads();
        if (threadIdx.x == 0) {
            int d = atomicAdd(&g_done, 1);
            if (d == DEC_BLOCKS - 1) {
                g_done = 0;
                __threadfence();
                *(volatile int*)&g_flag = 0;
            }
        }
        return;
    }

    // ================= ENCODER BLOCK (10) =================
    extern __shared__ float sm[];
    float* s_t    = sm;            // 144
    float* s_gatW = sm + 144;      // 48
    float* s_as   = sm + 192;      // 16
    float* s_ad   = sm + 208;      // 16
    float* s_teW  = sm + 224;      // 320  (16 rows * 20)
    float* s_teb  = sm + 544;      // 16
    float* s_pe   = sm + 560;      // 48
    float* s_qkvW = sm + 608;      // 1920 (2*48 rows * 20)
    float* s_qkvb = sm + 2528;     // 96
    float* s_outW = sm + 2624;     // 640  (2*16 rows * 20)
    float* s_outb = sm + 3264;     // 32
    float* s_ln1g = sm + 3296;     // 32
    float* s_ln1b = sm + 3328;     // 32
    float* s_ff1W = sm + 3360;     // 2560 (2*64 rows * 20)
    float* s_ff1b = sm + 5920;     // 128
    float* s_ff2W = sm + 6048;     // 2176 (2*16 rows * 68)
    float* s_ff2b = sm + 8224;     // 32
    float* s_ln2g = sm + 8256;     // 32
    float* s_ln2b = sm + 8288;     // 32
    // activations: token rows padded to stride 20 (float4-aligned, low conflict)
    float* A_h    = sm + 8320;     // 48*20 = 960
    float* A_al   = sm + 9280;     // 48*20 (alpha rows, [w*16+dst][20])
    float* A_xe   = sm + 10240;    // 960
    float* A_ctx  = sm + 11200;    // 960
    float* A_qkv  = sm + 12160;    // 48*49 = 2352 (odd stride -> conflict-free scalar)
    float* A_hid  = sm + 14512;    // 48*65 = 3120
    float* A_e    = sm + 17632;    // 96

    const int tid  = threadIdx.x;
    const int warp = tid >> 5;
    const int lane = tid & 31;
    const int g    = warp & 1;          // token group (lanes 0-31 / 32-47)
    const int tk   = g * 32 + lane;     // token id
    const int pp   = warp >> 1;         // warp-pair id 0..7
    const bool tok_ok = tk < 48;

    // ---- preload all weights to smem (one time, coalesced) ----
    for (int i = tid; i < 144; i += NT) s_t[i] = t[i];
    for (int i = tid; i < 48; i += NT)  s_gatW[i] = gat_W[i];
    if (tid < 16) { s_as[tid] = a_src[tid]; s_ad[tid] = a_dst[tid]; s_teb[tid] = te_b[tid]; }
    for (int i = tid; i < 256; i += NT)  s_teW[(i >> 4) * 20 + (i & 15)] = te_W[i];
    for (int i = tid; i < 48; i += NT)   s_pe[i] = pe[i];
    for (int i = tid; i < 1536; i += NT) s_qkvW[(i >> 4) * 20 + (i & 15)] = qkv_W[i];
    for (int i = tid; i < 96; i += NT)   s_qkvb[i] = qkv_b[i];
    for (int i = tid; i < 512; i += NT)  s_outW[(i >> 4) * 20 + (i & 15)] = out_W[i];
    if (tid < 32) {
        s_outb[tid] = out_b[tid];
        s_ln1g[tid] = ln1_g[tid]; s_ln1b[tid] = ln1_b[tid];
        s_ln2g[tid] = ln2_g[tid]; s_ln2b[tid] = ln2_b[tid];
        s_ff2b[tid] = ff2_b[tid];
    }
    for (int i = tid; i < 2048; i += NT) s_ff1W[(i >> 4) * 20 + (i & 15)] = ff1_W[i];
    for (int i = tid; i < 128; i += NT)  s_ff1b[i] = ff1_b[i];
    for (int i = tid; i < 2048; i += NT) s_ff2W[(i >> 6) * 68 + (i & 63)] = ff2_W[i];
    __syncthreads();

    // ---- GAT: h[tk][f] = x[tk] @ gat_W   (tiny: 3 FMA each) ----
    for (int idx = tid; idx < 768; idx += NT) {
        int tkx = idx >> 4, f = idx & 15;
        const float* xr = s_t + tkx * 3;
        A_h[tkx * 20 + f] = xr[0]*s_gatW[f] + xr[1]*s_gatW[16+f] + xr[2]*s_gatW[32+f];
    }
    __syncthreads();

    // ---- e_src / e_dst (96 dot16s) ----
    if (tid < 96) {
        int which = tid >= 48, idx = tid - which * 48;
        const float* a = which ? s_ad : s_as;
        const float4* r4 = (const float4*)(A_h + idx * 20);
        const float4* a4 = (const float4*)a;
        float s = 0.f;
#pragma unroll
        for (int i = 0; i < 4; i++) {
            float4 x = r4[i], y = a4[i];
            s += x.x*y.x + x.y*y.y + x.z*y.z + x.w*y.w;
        }
        A_e[tid] = s;
    }
    __syncthreads();

    // ---- alpha = softmax over sources, per (w,dst) ----
    if (tid < 48) {
        int w = tid >> 4;
        float ed = A_e[48 + tid];
        float vals[16], mx = -1e30f;
#pragma unroll
        for (int s = 0; s < 16; s++) {
            float e = A_e[w * 16 + s] + ed;
            e = (e > 0.f) ? e : 0.2f * e;
            vals[s] = e; mx = fmaxf(mx, e);
        }
        float sum = 0.f;
#pragma unroll
        for (int s = 0; s < 16; s++) { vals[s] = __expf(vals[s] - mx); sum += vals[s]; }
        float inv = 1.f / sum;
#pragma unroll
        for (int s = 0; s < 16; s++) A_al[tid * 20 + s] = vals[s] * inv;
    }
    __syncthreads();

    // ---- gat_out[w,dst,f] = elu( sum_s alpha[w,dst,s]*h[w,s,f] ) ----
    // warps 0..11: ww = warp>>2, f-group = warp&3; lane = dst (<16)
    if (warp < 12 && lane < 16) {
        int ww = warp >> 2, fg = warp & 3;
        float al[16];
        const float4* al4 = (const float4*)(A_al + (ww * 16 + lane) * 20);
#pragma unroll
        for (int i = 0; i < 4; i++) {
            float4 v = al4[i];
            al[4*i] = v.x; al[4*i+1] = v.y; al[4*i+2] = v.z; al[4*i+3] = v.w;
        }
#pragma unroll
        for (int i4 = 0; i4 < 4; i4++) {
            int f = fg * 4 + i4;
            float s = 0.f;
            const float* hc = A_h + ww * 320 + f;   // broadcast (warp-uniform addr)
#pragma unroll
            for (int ss = 0; ss < 16; ss++) s += al[ss] * hc[ss * 20];
            A_ctx[(ww * 16 + lane) * 20 + f] = (s > 0.f) ? s : (__expf(s) - 1.f);
        }
    }
    __syncthreads();

    // ---- xe = gat_out @ te_W^T + te_b + pe : lane=token, 2 outputs/lane ----
    if (tok_ok) {
        float x[16];
        const float4* x4 = (const float4*)(A_ctx + tk * 20);
#pragma unroll
        for (int i = 0; i < 4; i++) {
            float4 v = x4[i];
            x[4*i] = v.x; x[4*i+1] = v.y; x[4*i+2] = v.z; x[4*i+3] = v.w;
        }
        int w = tk >> 4;
#pragma unroll
        for (int i2 = 0; i2 < 2; i2++) {
            int d = pp + i2 * 8;
            const float* wd = s_teW + d * 20;      // broadcast
            float s = s_teb[d] + s_pe[w * 16 + d];
#pragma unroll
            for (int i = 0; i < 16; i++) s += x[i] * wd[i];
            A_xe[tk * 20 + d] = s;
        }
    }
    __syncthreads();

    const float inv_sqrt_hd = 0.35355339059327373f;

    for (int l = 0; l < 2; l++) {
        // ---- qkv: lane=token, 6 outputs/lane, weights broadcast ----
        if (tok_ok) {
            float x[16];
            const float4* x4 = (const float4*)(A_xe + tk * 20);
#pragma unroll
            for (int i = 0; i < 4; i++) {
                float4 v = x4[i];
                x[4*i] = v.x; x[4*i+1] = v.y; x[4*i+2] = v.z; x[4*i+3] = v.w;
            }
#pragma unroll
            for (int i6 = 0; i6 < 6; i6++) {
                int j = pp + i6 * 8;
                const float* wj = s_qkvW + l * 960 + j * 20;   // broadcast
                float s = s_qkvb[l * 48 + j];
#pragma unroll
                for (int i = 0; i < 16; i++) s += x[i] * wj[i];
                A_qkv[tk * 49 + j] = s;
            }
        }
        __syncthreads();

        // ---- attention: 96 units (b, head, query-pos) ----
        if (tid < 96) {
            int b = tid / 6, r = tid - b * 6;
            int hh = r / 3, qs = r - hh * 3;
            const float* q = A_qkv + (qs * 16 + b) * 49 + hh * 8;
            float sc[3], mx = -1e30f;
#pragma unroll
            for (int ks = 0; ks < 3; ks++) {
                const float* k = A_qkv + (ks * 16 + b) * 49 + 16 + hh * 8;
                float s = 0.f;
#pragma unroll
                for (int e = 0; e < 8; e++) s += q[e] * k[e];
                s *= inv_sqrt_hd;
                sc[ks] = s; mx = fmaxf(mx, s);
            }
            float sum = 0.f;
#pragma unroll
            for (int ks = 0; ks < 3; ks++) { sc[ks] = __expf(sc[ks] - mx); sum += sc[ks]; }
            float inv = 1.f / sum;
#pragma unroll
            for (int e = 0; e < 8; e++) {
                float c = 0.f;
#pragma unroll
                for (int ks = 0; ks < 3; ks++) c += sc[ks] * A_qkv[(ks * 16 + b) * 49 + 32 + hh * 8 + e];
                A_ctx[(qs * 16 + b) * 20 + hh * 8 + e] = c * inv;
            }
        }
        __syncthreads();

        // ---- out-proj + residual -> A_h ----
        if (tok_ok) {
            float x[16];
            const float4* x4 = (const float4*)(A_ctx + tk * 20);
#pragma unroll
            for (int i = 0; i < 4; i++) {
                float4 v = x4[i];
                x[4*i] = v.x; x[4*i+1] = v.y; x[4*i+2] = v.z; x[4*i+3] = v.w;
            }
#pragma unroll
            for (int i2 = 0; i2 < 2; i2++) {
                int d = pp + i2 * 8;
                const float* wd = s_outW + l * 320 + d * 20;   // broadcast
                float s = s_outb[l * 16 + d] + A_xe[tk * 20 + d];
#pragma unroll
                for (int i = 0; i < 16; i++) s += x[i] * wd[i];
                A_h[tk * 20 + d] = s;
            }
        }
        __syncthreads();

        // ---- LN1 -> A_xe ----
        if (tid < 48) {
            float x[16];
            const float4* r4 = (const float4*)(A_h + tid * 20);
#pragma unroll
            for (int i = 0; i < 4; i++) {
                float4 v = r4[i];
                x[4*i] = v.x; x[4*i+1] = v.y; x[4*i+2] = v.z; x[4*i+3] = v.w;
            }
            float m = 0.f;
#pragma unroll
            for (int e = 0; e < 16; e++) m += x[e];
            m *= 0.0625f;
            float v = 0.f;
#pragma unroll
            for (int e = 0; e < 16; e++) { float d = x[e] - m; v += d * d; }
            float rin = rsqrtf(v * 0.0625f + 1e-5f);
            const float* gg = s_ln1g + l * 16;
            const float* bb = s_ln1b + l * 16;
#pragma unroll
            for (int e = 0; e < 16; e++) A_xe[tid * 20 + e] = (x[e] - m) * rin * gg[e] + bb[e];
        }
        __syncthreads();

        // ---- ff1 (relu): lane=token, 8 outputs/lane ----
        if (tok_ok) {
            float x[16];
            const float4* x4 = (const float4*)(A_xe + tk * 20);
#pragma unroll
            for (int i = 0; i < 4; i++) {
                float4 v = x4[i];
                x[4*i] = v.x; x[4*i+1] = v.y; x[4*i+2] = v.z; x[4*i+3] = v.w;
            }
#pragma unroll
            for (int i8 = 0; i8 < 8; i8++) {
                int f = pp + i8 * 8;
                const float* wf = s_ff1W + l * 1280 + f * 20;   // broadcast
                float s = s_ff1b[l * 64 + f];
#pragma unroll
                for (int i = 0; i < 16; i++) s += x[i] * wf[i];
                A_hid[tk * 65 + f] = fmaxf(s, 0.f);
            }
        }
        __syncthreads();

        // ---- ff2 + residual -> A_h : lane=token, 2 outputs/lane ----
        if (tok_ok) {
            int d0 = pp, d1 = pp + 8;
            const float* hr = A_hid + tk * 65;                  // per-lane, conflict-free
            const float* w0 = s_ff2W + l * 1088 + d0 * 68;      // broadcast
            const float* w1 = s_ff2W + l * 1088 + d1 * 68;      // broadcast
            float a0 = s_ff2b[l * 16 + d0] + A_xe[tk * 20 + d0];
            float a1 = s_ff2b[l * 16 + d1] + A_xe[tk * 20 + d1];
#pragma unroll
            for (int f = 0; f < 64; f++) {
                float hv = hr[f];
                a0 += hv * w0[f];
                a1 += hv * w1[f];
            }
            A_h[tk * 20 + d0] = a0;
            A_h[tk * 20 + d1] = a1;
        }
        __syncthreads();

        // ---- LN2 -> A_xe ----
        if (tid < 48) {
            float x[16];
            const float4* r4 = (const float4*)(A_h + tid * 20);
#pragma unroll
            for (int i = 0; i < 4; i++) {
                float4 v = r4[i];
                x[4*i] = v.x; x[4*i+1] = v.y; x[4*i+2] = v.z; x[4*i+3] = v.w;
            }
            float m = 0.f;
#pragma unroll
            for (int e = 0; e < 16; e++) m += x[e];
            m *= 0.0625f;
            float v = 0.f;
#pragma unroll
            for (int e = 0; e < 16; e++) { float d = x[e] - m; v += d * d; }
            float rin = rsqrtf(v * 0.0625f + 1e-5f);
            const float* gg = s_ln2g + l * 16;
            const float* bb = s_ln2b + l * 16;
#pragma unroll
            for (int e = 0; e < 16; e++) A_xe[tid * 20 + e] = (x[e] - m) * rin * gg[e] + bb[e];
        }
        __syncthreads();
    }

    // ---- latent (host-major) to global, release flag ----
    for (int idx = tid; idx < 768; idx += NT) {
        int w = idx >> 8, rem = idx & 255, n = rem >> 4, d = rem & 15;
        g_latent[n * 48 + w * 16 + d] = A_xe[(w * 16 + n) * 20 + d];
    }
    __threadfence();
    __syncthreads();
    if (tid == 0) *(volatile int*)&g_flag = 1;
}

extern "C" void kernel_launch(void* const* d_in, const int* in_sizes, int n_in,
                              void* d_out, int out_size) {
    const int smem_bytes = 17728 * 4;
    cudaFuncSetAttribute(fused_kernel, cudaFuncAttributeMaxDynamicSharedMemorySize, smem_bytes);
    fused_kernel<<<DEC_BLOCKS + 1, NT, smem_bytes>>>(
        (const float*)d_in[0],
        (const float*)d_in[2], (const float*)d_in[3], (const float*)d_in[4],
        (const float*)d_in[5], (const float*)d_in[6], (const float*)d_in[7],
        (const float*)d_in[8], (const float*)d_in[9],
        (const float*)d_in[10], (const float*)d_in[11],
        (const float*)d_in[12], (const float*)d_in[13],
        (const float*)d_in[14], (const float*)d_in[15],
        (const float*)d_in[16], (const float*)d_in[17],
        (const float*)d_in[18], (const float*)d_in[19],
        (const float*)d_in[20], (const float*)d_in[21],
        (const float*)d_in[22], (const float*)d_in[23],
        (float*)d_out);
}